// round 1
// baseline (speedup 1.0000x reference)
#include <cuda_runtime.h>

#define NBINS 36
#define PS 32
#define WARPS_PER_BLOCK 8
#define THREADS (WARPS_PER_BLOCK * 32)

// float(2*pi) = 6.2831855f (0x40C90FDB), matches jnp float32 constant
#define TWO_PI_F 6.283185307179586f
#define PI_F 3.14159265358979f

__global__ __launch_bounds__(THREADS)
void orient_kernel(const float* __restrict__ x,
                   const float* __restrict__ gxw,
                   const float* __restrict__ gyw,
                   const float* __restrict__ smw,
                   const float* __restrict__ gk,
                   float* __restrict__ out,
                   int B)
{
    __shared__ float shist[WARPS_PER_BLOCK][NBINS];

    const int warp = threadIdx.x >> 5;
    const int lane = threadIdx.x & 31;
    const int patch = blockIdx.x * WARPS_PER_BLOCK + warp;
    if (patch >= B) return;

    // zero this warp's histogram (36 bins, 32 lanes)
    shist[warp][lane] = 0.0f;
    if (lane < NBINS - 32) shist[warp][32 + lane] = 0.0f;
    __syncwarp();

    // gradient weights (tiny, L1-resident)
    const float wx0 = __ldg(gxw + 0), wx1 = __ldg(gxw + 1), wx2 = __ldg(gxw + 2);
    const float wy0 = __ldg(gyw + 0), wy1 = __ldg(gyw + 1), wy2 = __ldg(gyw + 2);

    // preload the whole patch column for this lane: 32 coalesced row loads
    const float* p = x + (size_t)patch * (PS * PS) + lane;
    float v[PS];
#pragma unroll
    for (int r = 0; r < PS; ++r) v[r] = __ldg(p + r * PS);

#pragma unroll
    for (int r = 0; r < PS; ++r) {
        const float b = v[r];
        const float a = v[(r == 0) ? 0 : r - 1];          // up (replicate)
        const float c = v[(r == PS - 1) ? PS - 1 : r + 1]; // down (replicate)

        float left  = __shfl_up_sync(0xffffffffu, b, 1);
        float right = __shfl_down_sync(0xffffffffu, b, 1);
        if (lane == 0)  left  = b;   // replicate pad
        if (lane == 31) right = b;

        const float gx = wx0 * left + wx1 * b + wx2 * right;
        const float gy = wy0 * a    + wy1 * b + wy2 * c;

        const float g = __ldg(gk + r * PS + lane);
        const float mag = sqrtf(gx * gx + gy * gy + 1e-10f) * g;

        if (mag > 0.001f) {
            const float ori = atan2f(gy, gx);
            // jnp.mod(ori, 2pi): ori in (-pi, pi] -> add 2pi if negative
            const float m = (ori < 0.0f) ? (ori + TWO_PI_F) : ori;
            // o_big = NBINS * m / TWO_PI (reference op order, IEEE divide)
            const float ob = (36.0f * m) / TWO_PI_F;
            const float f = floorf(ob);
            const float wo1 = ob - f;
            int bin = (int)f;
            if (bin >= NBINS) bin -= NBINS;   // handles m rounding up to 2pi
            atomicAdd(&shist[warp][bin], (1.0f - wo1) * mag);
        }
    }
    __syncwarp();

    // smoothing (conv3, zero pad) + argmax over 36 bins, in-warp
    const float s0 = __ldg(smw + 0), s1 = __ldg(smw + 1), s2 = __ldg(smw + 2);
    const float inv = 1.0f / (float)(PS * PS);

    float bestv;
    int besti;
    {
        const int i = lane;                       // bins 0..31
        const float hm = (i > 0) ? shist[warp][i - 1] * inv : 0.0f;
        const float hc = shist[warp][i] * inv;
        const float hp = shist[warp][i + 1] * inv; // i+1 <= 32 < 36, valid
        bestv = s0 * hm + s1 * hc + s2 * hp;
        besti = i;
    }
    if (lane < NBINS - 32) {                      // bins 32..35
        const int i = lane + 32;
        const float hm = shist[warp][i - 1] * inv;
        const float hc = shist[warp][i] * inv;
        const float hp = (i + 1 < NBINS) ? shist[warp][i + 1] * inv : 0.0f;
        const float sm = s0 * hm + s1 * hc + s2 * hp;
        if (sm > bestv) { bestv = sm; besti = i; } // strict >: lower index wins ties
    }
    // warp argmax, lowest index on ties (matches jnp.argmax)
#pragma unroll
    for (int off = 16; off > 0; off >>= 1) {
        const float ov = __shfl_down_sync(0xffffffffu, bestv, off);
        const int   oi = __shfl_down_sync(0xffffffffu, besti, off);
        if (ov > bestv || (ov == bestv && oi < besti)) { bestv = ov; besti = oi; }
    }

    if (lane == 0) {
        const float ang = -((TWO_PI_F * (float)besti) / 36.0f - PI_F);
        out[patch] = ang;
    }
}

extern "C" void kernel_launch(void* const* d_in, const int* in_sizes, int n_in,
                              void* d_out, int out_size)
{
    const float* x   = (const float*)d_in[0];
    const float* gxw = (const float*)d_in[1];
    const float* gyw = (const float*)d_in[2];
    const float* smw = (const float*)d_in[3];
    const float* gk  = (const float*)d_in[4];
    float* out = (float*)d_out;

    const int B = out_size;  // one angle per patch
    const int grid = (B + WARPS_PER_BLOCK - 1) / WARPS_PER_BLOCK;
    orient_kernel<<<grid, THREADS>>>(x, gxw, gyw, smw, gk, out, B);
}

// round 3
// speedup vs baseline: 1.0702x; 1.0702x over previous
#include <cuda_runtime.h>

#define NBINS 36
#define PS 32
#define WARPS_PER_BLOCK 8
#define THREADS (WARPS_PER_BLOCK * 32)
#define CHUNK 8

#define TWO_PI_F 6.283185307179586f
#define PI_F     3.14159265358979f

__global__ __launch_bounds__(THREADS, 6)
void orient_kernel(const float* __restrict__ x,
                   const float* __restrict__ gxw,
                   const float* __restrict__ gyw,
                   const float* __restrict__ smw,
                   const float* __restrict__ gk,
                   float* __restrict__ out,
                   int B)
{
    __shared__ float shist[WARPS_PER_BLOCK][NBINS];

    const int warp = threadIdx.x >> 5;
    const int lane = threadIdx.x & 31;
    const int patch = blockIdx.x * WARPS_PER_BLOCK + warp;
    if (patch >= B) return;

    shist[warp][lane] = 0.0f;
    if (lane < NBINS - 32) shist[warp][32 + lane] = 0.0f;
    __syncwarp();

    const float wx0 = __ldg(gxw + 0), wx1 = __ldg(gxw + 1), wx2 = __ldg(gxw + 2);
    const float wy0 = __ldg(gyw + 0), wy1 = __ldg(gyw + 1), wy2 = __ldg(gyw + 2);

    const float* p  = x + (size_t)patch * (PS * PS) + lane;
    const float* gp = gk + lane;

    // process rows in chunks of CHUNK; v window holds [c0-1 .. c0+CHUNK] (clamped)
#pragma unroll
    for (int c0 = 0; c0 < PS; c0 += CHUNK) {
        float v[CHUNK + 2];
#pragma unroll
        for (int i = 0; i < CHUNK + 2; ++i) {
            int r = c0 - 1 + i;
            r = (r < 0) ? 0 : ((r > PS - 1) ? PS - 1 : r);
            v[i] = __ldg(p + r * PS);
        }

#pragma unroll
        for (int i = 0; i < CHUNK; ++i) {
            const int r = c0 + i;
            const float b    = v[i + 1];
            const float a_up = v[i];       // row r-1 (replicate-clamped)
            const float c_dn = v[i + 2];   // row r+1 (replicate-clamped)

            // shfl up/down clamp at warp edges -> returns own value = replicate pad
            const float left  = __shfl_up_sync(0xffffffffu, b, 1);
            const float right = __shfl_down_sync(0xffffffffu, b, 1);

            const float gx = wx0 * left + wx1 * b    + wx2 * right;
            const float gy = wy0 * a_up + wy1 * b    + wy2 * c_dn;

            const float g = __ldg(gp + r * PS);
            const float mag = sqrtf(gx * gx + gy * gy + 1e-10f) * g;

            if (mag > 0.001f) {
                const float ori = atan2f(gy, gx);                  // must stay libdevice-exact
                const float m = (ori < 0.0f) ? (ori + TWO_PI_F) : ori;
                const float ob = (36.0f * m) / TWO_PI_F;           // IEEE divide, reference order
                const float f = floorf(ob);
                const float wo1 = ob - f;
                int bin = (int)f;
                if (bin >= NBINS) bin -= NBINS;
                atomicAdd(&shist[warp][bin], (1.0f - wo1) * mag);
            }
        }
    }
    __syncwarp();

    // smoothing (conv3, zero pad) + argmax over 36 bins, in-warp
    const float s0 = __ldg(smw + 0), s1 = __ldg(smw + 1), s2 = __ldg(smw + 2);
    const float inv = 1.0f / (float)(PS * PS);

    float bestv;
    int besti;
    {
        const int i = lane;                         // bins 0..31
        const float hm = (i > 0) ? shist[warp][i - 1] * inv : 0.0f;
        const float hc = shist[warp][i] * inv;
        const float hp = shist[warp][i + 1] * inv;  // i+1 <= 32 < 36, valid
        bestv = s0 * hm + s1 * hc + s2 * hp;
        besti = i;
    }
    if (lane < NBINS - 32) {                        // bins 32..35
        const int i = lane + 32;
        const float hm = shist[warp][i - 1] * inv;
        const float hc = shist[warp][i] * inv;
        const float hp = (i + 1 < NBINS) ? shist[warp][i + 1] * inv : 0.0f;
        const float sm = s0 * hm + s1 * hc + s2 * hp;
        if (sm > bestv) { bestv = sm; besti = i; }  // strict >: lower index wins ties
    }
#pragma unroll
    for (int off = 16; off > 0; off >>= 1) {
        const float ov = __shfl_down_sync(0xffffffffu, bestv, off);
        const int   oi = __shfl_down_sync(0xffffffffu, besti, off);
        if (ov > bestv || (ov == bestv && oi < besti)) { bestv = ov; besti = oi; }
    }

    if (lane == 0) {
        out[patch] = -((TWO_PI_F * (float)besti) / 36.0f - PI_F);
    }
}

extern "C" void kernel_launch(void* const* d_in, const int* in_sizes, int n_in,
                              void* d_out, int out_size)
{
    const float* x   = (const float*)d_in[0];
    const float* gxw = (const float*)d_in[1];
    const float* gyw = (const float*)d_in[2];
    const float* smw = (const float*)d_in[3];
    const float* gk  = (const float*)d_in[4];
    float* out = (float*)d_out;

    const int B = out_size;
    const int grid = (B + WARPS_PER_BLOCK - 1) / WARPS_PER_BLOCK;
    orient_kernel<<<grid, THREADS>>>(x, gxw, gyw, smw, gk, out, B);
}